// round 4
// baseline (speedup 1.0000x reference)
#include <cuda_runtime.h>
#include <math.h>
#include <float.h>

#define NN   50000
#define EE   800000
#define EPSL 1e-5f
#define MAXD 256
#define NBLK 49   // ceil(NN/1024)

// ---------------- scratch (device globals; no allocation) ----------------
__device__ float g_deg[NN];
__device__ float g_logdeg[NN];
__device__ float g_amp[NN];
__device__ float g_att[NN];
__device__ float g_sumlog;
__device__ int   g_off[NN + 1];
__device__ int   g_incl[NN];
__device__ int   g_cur[NN];
__device__ int   g_srcs[EE];
__device__ int   g_bsum[NBLK];
__device__ float g_aggs[(size_t)NN * 4 * MAXD];   // [N][4d], d<=256
__device__ float g_x[(size_t)NN * MAXD];          // normalized layer input
__device__ float g_h[(size_t)NN * MAXD];          // relu(linear) output
__device__ float g_colsum[MAXD];
__device__ float g_colssq[MAXD];
__device__ float g_scale[MAXD];
__device__ float g_shift[MAXD];

// ---------------- prologue: degrees, scalers, CSR ----------------
__global__ void k_init() {
    int i = blockIdx.x * blockDim.x + threadIdx.x;
    if (i < NN) { g_deg[i] = 0.f; g_cur[i] = 0; }
    if (i == 0) g_sumlog = 0.f;
}

__global__ void k_deg(const int* __restrict__ ei) {
    int e = blockIdx.x * blockDim.x + threadIdx.x;
    if (e < EE) atomicAdd(&g_deg[ei[EE + e]], 1.f);
}

__global__ void k_logdeg() {
    int i = blockIdx.x * blockDim.x + threadIdx.x;
    float v = 0.f;
    if (i < NN) { v = log1pf(g_deg[i]); g_logdeg[i] = v; }
    #pragma unroll
    for (int o = 16; o > 0; o >>= 1) v += __shfl_down_sync(0xFFFFFFFFu, v, o);
    if ((threadIdx.x & 31) == 0) atomicAdd(&g_sumlog, v);
}

__global__ void k_ampatt() {
    int i = blockIdx.x * blockDim.x + threadIdx.x;
    if (i >= NN) return;
    float delta = g_sumlog / (float)NN;
    float ld = g_logdeg[i];
    g_amp[i] = ld / delta;
    g_att[i] = (ld > 0.f) ? (delta / fmaxf(ld, 1e-6f)) : 1.f;
}

__global__ void k_scan1() {            // 1024 threads/block, NBLK blocks
    __shared__ int s[1024];
    int tid = threadIdx.x;
    int i = blockIdx.x * 1024 + tid;
    int v = (i < NN) ? (int)(g_deg[i] + 0.5f) : 0;
    s[tid] = v;
    __syncthreads();
    for (int d = 1; d < 1024; d <<= 1) {
        int t = (tid >= d) ? s[tid - d] : 0;
        __syncthreads();
        s[tid] += t;
        __syncthreads();
    }
    if (i < NN) g_incl[i] = s[tid];
    if (tid == 1023) g_bsum[blockIdx.x] = s[1023];
}

__global__ void k_scan2() {
    if (threadIdx.x == 0) {
        int run = 0;
        for (int b = 0; b < NBLK; b++) { int t = g_bsum[b]; g_bsum[b] = run; run += t; }
    }
}

__global__ void k_scan3() {
    int i = blockIdx.x * blockDim.x + threadIdx.x;
    if (i < NN) {
        int d = (int)(g_deg[i] + 0.5f);
        g_off[i] = g_bsum[i >> 10] + g_incl[i] - d;
    }
    if (i == 0) g_off[NN] = EE;
}

__global__ void k_csr(const int* __restrict__ ei) {
    int e = blockIdx.x * blockDim.x + threadIdx.x;
    if (e >= EE) return;
    int d = ei[EE + e];
    int p = atomicAdd(&g_cur[d], 1);
    g_srcs[g_off[d] + p] = ei[e];
}

// ---------------- PNA aggregation: one warp per node ----------------
template <int DJ>
__global__ void k_agg(const float* __restrict__ x) {
    const int d = DJ * 32;
    int gw = (blockIdx.x * blockDim.x + threadIdx.x) >> 5;
    int lane = threadIdx.x & 31;
    if (gw >= NN) return;
    int beg = g_off[gw], end = g_off[gw + 1];
    float sum[DJ], ssq[DJ], mn[DJ], mx[DJ];
    #pragma unroll
    for (int j = 0; j < DJ; j++) { sum[j] = 0.f; ssq[j] = 0.f; mn[j] = FLT_MAX; mx[j] = -FLT_MAX; }
    for (int e = beg; e < end; e++) {
        const float* row = x + (size_t)g_srcs[e] * d;
        #pragma unroll
        for (int j = 0; j < DJ; j++) {
            float v = __ldg(row + lane + 32 * j);
            sum[j] += v; ssq[j] += v * v;
            mn[j] = fminf(mn[j], v); mx[j] = fmaxf(mx[j], v);
        }
    }
    float kf  = (float)(end - beg);
    float inv = 1.f / fmaxf(kf, 1.f);
    float* ag = g_aggs + (size_t)gw * 4 * d;
    #pragma unroll
    for (int j = 0; j < DJ; j++) {
        int f = lane + 32 * j;
        float mean = sum[j] * inv;
        float msq  = ssq[j] * inv;
        float sd   = sqrtf(fmaxf(msq - mean * mean, 0.f) + EPSL);
        ag[f]         = mean;
        ag[d + f]     = (kf > 0.f) ? mn[j] : 0.f;
        ag[2 * d + f] = (kf > 0.f) ? mx[j] : 0.f;
        ag[3 * d + f] = sd;
    }
}

// ---------------- fused feat-build + GEMM + bias + ReLU ----------------
// C[N, dout] = feat @ W + b, feat = [x | aggs | aggs*amp | aggs*att]
template <int BN>
__global__ void __launch_bounds__(2 * BN)
k_gemm(const float* __restrict__ x, const float* __restrict__ W,
       const float* __restrict__ bias, float* __restrict__ h,
       int d, int dout) {
    const int BM = 128, BK = 16, NT = 2 * BN;
    __shared__ __align__(16) float As[BK][BM];
    __shared__ __align__(16) float Bs[BK][BN];

    int tid = threadIdx.x;
    int tm = tid & 15;       // 0..15 -> 8 rows each
    int tn = tid >> 4;       // 0..(BN/8 - 1)
    int row0 = blockIdx.x * BM;
    int n0 = blockIdx.y * BN;
    int K = 13 * d;

    float acc[8][8];
    #pragma unroll
    for (int i = 0; i < 8; i++)
        #pragma unroll
        for (int j = 0; j < 8; j++) acc[i][j] = 0.f;

    for (int k0 = 0; k0 < K; k0 += BK) {
        // --- A tile: each thread loads float4 chunks (coalesced along k) ---
        #pragma unroll
        for (int e = tid; e < BM * BK / 4; e += NT) {
            int m = e >> 2;
            int kq = (e & 3) * 4;
            int row = row0 + m;
            float4 v = make_float4(0.f, 0.f, 0.f, 0.f);
            if (row < NN) {
                int k = k0 + kq;
                if (k < d) {
                    v = *(const float4*)(x + (size_t)row * d + k);
                } else {
                    int a = k - d;
                    float s; int idx;
                    if (a < 4 * d)      { s = 1.f;        idx = a; }
                    else if (a < 8 * d) { s = g_amp[row]; idx = a - 4 * d; }
                    else                { s = g_att[row]; idx = a - 8 * d; }
                    float4 t4 = *(const float4*)(g_aggs + (size_t)row * 4 * d + idx);
                    v = make_float4(t4.x * s, t4.y * s, t4.z * s, t4.w * s);
                }
            }
            As[kq][m] = v.x; As[kq + 1][m] = v.y; As[kq + 2][m] = v.z; As[kq + 3][m] = v.w;
        }
        // --- B tile (coalesced float4) ---
        #pragma unroll
        for (int e = tid; e < BK * BN / 4; e += NT) {
            int kk = e / (BN / 4);
            int n = (e % (BN / 4)) * 4;
            *(float4*)&Bs[kk][n] = *(const float4*)(W + (size_t)(k0 + kk) * dout + n0 + n);
        }
        __syncthreads();

        #pragma unroll
        for (int kk = 0; kk < BK; kk++) {
            float4 a0 = *(const float4*)&As[kk][tm * 8];
            float4 a1 = *(const float4*)&As[kk][tm * 8 + 4];
            float4 b0 = *(const float4*)&Bs[kk][tn * 8];
            float4 b1 = *(const float4*)&Bs[kk][tn * 8 + 4];
            float aa[8] = {a0.x, a0.y, a0.z, a0.w, a1.x, a1.y, a1.z, a1.w};
            float bb[8] = {b0.x, b0.y, b0.z, b0.w, b1.x, b1.y, b1.z, b1.w};
            #pragma unroll
            for (int i = 0; i < 8; i++)
                #pragma unroll
                for (int j = 0; j < 8; j++)
                    acc[i][j] += aa[i] * bb[j];
        }
        __syncthreads();
    }

    float bv[8];
    #pragma unroll
    for (int j = 0; j < 8; j++) bv[j] = bias[n0 + tn * 8 + j];
    #pragma unroll
    for (int i = 0; i < 8; i++) {
        int r = row0 + tm * 8 + i;
        if (r < NN) {
            float4 o0, o1;
            o0.x = fmaxf(acc[i][0] + bv[0], 0.f);
            o0.y = fmaxf(acc[i][1] + bv[1], 0.f);
            o0.z = fmaxf(acc[i][2] + bv[2], 0.f);
            o0.w = fmaxf(acc[i][3] + bv[3], 0.f);
            o1.x = fmaxf(acc[i][4] + bv[4], 0.f);
            o1.y = fmaxf(acc[i][5] + bv[5], 0.f);
            o1.z = fmaxf(acc[i][6] + bv[6], 0.f);
            o1.w = fmaxf(acc[i][7] + bv[7], 0.f);
            float* hp = h + (size_t)r * dout + n0 + tn * 8;
            *(float4*)hp = o0;
            *(float4*)(hp + 4) = o1;
        }
    }
}

// ---------------- BatchNorm ----------------
__global__ void k_zerocols() {
    int i = threadIdx.x;
    g_colsum[i] = 0.f; g_colssq[i] = 0.f;
}

__global__ void k_stats(const float* __restrict__ h, int dout) {
    int col = threadIdx.x;           // blockDim.x == dout
    int r0 = blockIdx.x * 256;
    int r1 = min(r0 + 256, NN);
    float s = 0.f, q = 0.f;
    for (int r = r0; r < r1; r++) {
        float v = h[(size_t)r * dout + col];
        s += v; q += v * v;
    }
    atomicAdd(&g_colsum[col], s);
    atomicAdd(&g_colssq[col], q);
}

__global__ void k_bnfinal(const float* __restrict__ gamma, const float* __restrict__ beta, int dout) {
    int c = threadIdx.x;
    if (c >= dout) return;
    float m = g_colsum[c] / (float)NN;
    float var = fmaxf(g_colssq[c] / (float)NN - m * m, 0.f);
    float sc = gamma[c] * rsqrtf(var + EPSL);
    g_scale[c] = sc;
    g_shift[c] = beta[c] - m * sc;
}

__global__ void k_norm(const float* __restrict__ h, float* __restrict__ xo, int dout_mask, int total) {
    int i = blockIdx.x * blockDim.x + threadIdx.x;
    if (i >= total) return;
    int c = i & dout_mask;
    xo[i] = h[i] * g_scale[c] + g_shift[c];
}

// ---------------- classifier ----------------
__global__ void k_cls(const float* __restrict__ Wc, const float* __restrict__ bc, float* __restrict__ out) {
    __shared__ float sw[64 * 10];
    __shared__ float sb[10];
    for (int i = threadIdx.x; i < 640; i += blockDim.x) sw[i] = Wc[i];
    if (threadIdx.x < 10) sb[threadIdx.x] = bc[threadIdx.x];
    __syncthreads();
    int v = blockIdx.x * blockDim.x + threadIdx.x;
    if (v >= NN) return;
    const float* xr = g_x + (size_t)v * 64;
    float acc[10];
    #pragma unroll
    for (int c = 0; c < 10; c++) acc[c] = sb[c];
    #pragma unroll
    for (int f = 0; f < 64; f++) {
        float xv = xr[f];
        #pragma unroll
        for (int c = 0; c < 10; c++) acc[c] += xv * sw[f * 10 + c];
    }
    #pragma unroll
    for (int c = 0; c < 10; c++) out[(size_t)v * 10 + c] = acc[c];
}

// ---------------- launch ----------------
extern "C" void kernel_launch(void* const* d_in, const int* in_sizes, int n_in,
                              void* d_out, int out_size) {
    const float* x0 = (const float*)d_in[0];
    const int*   ei = (const int*)d_in[1];
    const float* W[4]  = {(const float*)d_in[2],  (const float*)d_in[6],
                          (const float*)d_in[10], (const float*)d_in[14]};
    const float* b[4]  = {(const float*)d_in[3],  (const float*)d_in[7],
                          (const float*)d_in[11], (const float*)d_in[15]};
    const float* ga[4] = {(const float*)d_in[4],  (const float*)d_in[8],
                          (const float*)d_in[12], (const float*)d_in[16]};
    const float* be[4] = {(const float*)d_in[5],  (const float*)d_in[9],
                          (const float*)d_in[13], (const float*)d_in[17]};
    const float* Wc = (const float*)d_in[18];
    const float* bc = (const float*)d_in[19];
    float* out = (float*)d_out;

    float *px, *ph;
    cudaGetSymbolAddress((void**)&px, g_x);
    cudaGetSymbolAddress((void**)&ph, g_h);

    const int TB = 256;
    const int NB_N = (NN + TB - 1) / TB;      // 196
    const int NB_E = (EE + TB - 1) / TB;      // 3125

    // prologue (graph structure is fixed across layers)
    k_init<<<NB_N, TB>>>();
    k_deg<<<NB_E, TB>>>(ei);
    k_logdeg<<<NB_N, TB>>>();
    k_ampatt<<<NB_N, TB>>>();
    k_scan1<<<NBLK, 1024>>>();
    k_scan2<<<1, 32>>>();
    k_scan3<<<NB_N, TB>>>();
    k_csr<<<NB_E, TB>>>(ei);

    const int dims[5]  = {64, 128, 256, 128, 64};  // d_in per layer, last = cls input
    const int AGG_B = (NN * 32 + TB - 1) / TB;     // 6250 (warp per node)
    const int GEMM_MB = (NN + 127) / 128;          // 391

    for (int l = 0; l < 4; l++) {
        int d = dims[l], dout = dims[l + 1];
        const float* xin = (l == 0) ? x0 : px;

        switch (d) {
            case 64:  k_agg<2><<<AGG_B, TB>>>(xin); break;
            case 128: k_agg<4><<<AGG_B, TB>>>(xin); break;
            case 256: k_agg<8><<<AGG_B, TB>>>(xin); break;
        }

        if (dout >= 128) {
            dim3 grid(GEMM_MB, dout / 128);
            k_gemm<128><<<grid, 256>>>(xin, W[l], b[l], ph, d, dout);
        } else {
            dim3 grid(GEMM_MB, 1);
            k_gemm<64><<<grid, 128>>>(xin, W[l], b[l], ph, d, dout);
        }

        k_zerocols<<<1, MAXD>>>();
        k_stats<<<(NN + 255) / 256, dout>>>(ph, dout);
        k_bnfinal<<<1, MAXD>>>(ga[l], be[l], dout);

        int total = NN * dout;
        k_norm<<<(total + TB - 1) / TB, TB>>>(ph, px, dout - 1, total);
    }

    k_cls<<<NB_N, TB>>>(Wc, bc, out);
}

// round 8
// speedup vs baseline: 1.0063x; 1.0063x over previous
#include <cuda_runtime.h>
#include <math.h>
#include <float.h>

#define NN   50000
#define EE   800000
#define EPSL 1e-5f
#define MAXD 256
#define NBLK 49   // ceil(NN/1024)

// ---------------- scratch (device globals; no allocation) ----------------
__device__ float g_deg[NN];
__device__ float g_logdeg[NN];
__device__ float g_amp[NN];
__device__ float g_att[NN];
__device__ float g_sumlog;
__device__ int   g_off[NN + 1];
__device__ int   g_incl[NN];
__device__ int   g_cur[NN];
__device__ int   g_srcs[EE];
__device__ int   g_bsum[NBLK];
__device__ float g_aggs[(size_t)NN * 4 * MAXD];   // [N][4d], d<=256
__device__ float g_x[(size_t)NN * MAXD];          // normalized layer input
__device__ float g_h[(size_t)NN * MAXD];          // relu(linear) output
__device__ float g_colsum[MAXD];
__device__ float g_colssq[MAXD];
__device__ float g_scale[MAXD];
__device__ float g_shift[MAXD];

// ---------------- prologue: degrees, scalers, CSR ----------------
__global__ void k_init() {
    int i = blockIdx.x * blockDim.x + threadIdx.x;
    if (i < NN) { g_deg[i] = 0.f; g_cur[i] = 0; }
    if (i == 0) g_sumlog = 0.f;
}

__global__ void k_deg(const int* __restrict__ ei) {
    int e = blockIdx.x * blockDim.x + threadIdx.x;
    if (e < EE) atomicAdd(&g_deg[ei[EE + e]], 1.f);
}

__global__ void k_logdeg() {
    int i = blockIdx.x * blockDim.x + threadIdx.x;
    float v = 0.f;
    if (i < NN) { v = log1pf(g_deg[i]); g_logdeg[i] = v; }
    #pragma unroll
    for (int o = 16; o > 0; o >>= 1) v += __shfl_down_sync(0xFFFFFFFFu, v, o);
    if ((threadIdx.x & 31) == 0) atomicAdd(&g_sumlog, v);
}

__global__ void k_ampatt() {
    int i = blockIdx.x * blockDim.x + threadIdx.x;
    if (i >= NN) return;
    float delta = g_sumlog / (float)NN;
    float ld = g_logdeg[i];
    g_amp[i] = ld / delta;
    g_att[i] = (ld > 0.f) ? (delta / fmaxf(ld, 1e-6f)) : 1.f;
}

__global__ void k_scan1() {            // 1024 threads/block, NBLK blocks
    __shared__ int s[1024];
    int tid = threadIdx.x;
    int i = blockIdx.x * 1024 + tid;
    int v = (i < NN) ? (int)(g_deg[i] + 0.5f) : 0;
    s[tid] = v;
    __syncthreads();
    for (int d = 1; d < 1024; d <<= 1) {
        int t = (tid >= d) ? s[tid - d] : 0;
        __syncthreads();
        s[tid] += t;
        __syncthreads();
    }
    if (i < NN) g_incl[i] = s[tid];
    if (tid == 1023) g_bsum[blockIdx.x] = s[1023];
}

__global__ void k_scan2() {
    if (threadIdx.x == 0) {
        int run = 0;
        for (int b = 0; b < NBLK; b++) { int t = g_bsum[b]; g_bsum[b] = run; run += t; }
    }
}

__global__ void k_scan3() {
    int i = blockIdx.x * blockDim.x + threadIdx.x;
    if (i < NN) {
        int d = (int)(g_deg[i] + 0.5f);
        g_off[i] = g_bsum[i >> 10] + g_incl[i] - d;
    }
    if (i == 0) g_off[NN] = EE;
}

__global__ void k_csr(const int* __restrict__ ei) {
    int e = blockIdx.x * blockDim.x + threadIdx.x;
    if (e >= EE) return;
    int d = ei[EE + e];
    int p = atomicAdd(&g_cur[d], 1);
    g_srcs[g_off[d] + p] = ei[e];
}

// ---------------- PNA aggregation: one warp per node ----------------
template <int DJ>
__global__ void k_agg(const float* __restrict__ x) {
    const int d = DJ * 32;
    int gw = (blockIdx.x * blockDim.x + threadIdx.x) >> 5;
    int lane = threadIdx.x & 31;
    if (gw >= NN) return;
    int beg = g_off[gw], end = g_off[gw + 1];
    float sum[DJ], ssq[DJ], mn[DJ], mx[DJ];
    #pragma unroll
    for (int j = 0; j < DJ; j++) { sum[j] = 0.f; ssq[j] = 0.f; mn[j] = FLT_MAX; mx[j] = -FLT_MAX; }
    for (int e = beg; e < end; e++) {
        const float* row = x + (size_t)g_srcs[e] * d;
        #pragma unroll
        for (int j = 0; j < DJ; j++) {
            float v = __ldg(row + lane + 32 * j);
            sum[j] += v; ssq[j] += v * v;
            mn[j] = fminf(mn[j], v); mx[j] = fmaxf(mx[j], v);
        }
    }
    float kf  = (float)(end - beg);
    float inv = 1.f / fmaxf(kf, 1.f);
    float* ag = g_aggs + (size_t)gw * 4 * d;
    #pragma unroll
    for (int j = 0; j < DJ; j++) {
        int f = lane + 32 * j;
        float mean = sum[j] * inv;
        float msq  = ssq[j] * inv;
        float sd   = sqrtf(fmaxf(msq - mean * mean, 0.f) + EPSL);
        ag[f]         = mean;
        ag[d + f]     = (kf > 0.f) ? mn[j] : 0.f;
        ag[2 * d + f] = (kf > 0.f) ? mx[j] : 0.f;
        ag[3 * d + f] = sd;
    }
}

// ---------------- fused feat-build + GEMM + bias + ReLU ----------------
// C[N, dout] = feat @ W + b, feat = [x | aggs | aggs*amp | aggs*att]
// Microkernel uses packed fma.rn.f32x2 (SASS FFMA2): 2 fp32 FMA per fma-pipe
// issue slot -> 2x the scalar FFMA flops ceiling. Bitwise identical math.
template <int BN>
__global__ void __launch_bounds__(2 * BN, 2)
k_gemm(const float* __restrict__ x, const float* __restrict__ W,
       const float* __restrict__ bias, float* __restrict__ h,
       int d, int dout) {
    const int BM = 128, BK = 16, NT = 2 * BN;
    __shared__ __align__(16) float As[BK][BM];
    __shared__ __align__(16) float Bs[BK][BN];

    int tid = threadIdx.x;
    int tm = tid & 15;       // 0..15 -> 8 rows each
    int tn = tid >> 4;       // 0..(BN/8 - 1)
    int row0 = blockIdx.x * BM;
    int n0 = blockIdx.y * BN;
    int K = 13 * d;

    // acc2[i][j] holds packed pair (C[i][2j], C[i][2j+1])
    unsigned long long acc2[8][4];
    #pragma unroll
    for (int i = 0; i < 8; i++)
        #pragma unroll
        for (int j = 0; j < 4; j++) acc2[i][j] = 0ULL;   // (+0.0f, +0.0f)

    for (int k0 = 0; k0 < K; k0 += BK) {
        // --- A tile: each thread loads float4 chunks (coalesced along k) ---
        #pragma unroll
        for (int e = tid; e < BM * BK / 4; e += NT) {
            int m = e >> 2;
            int kq = (e & 3) * 4;
            int row = row0 + m;
            float4 v = make_float4(0.f, 0.f, 0.f, 0.f);
            if (row < NN) {
                int k = k0 + kq;
                if (k < d) {
                    v = *(const float4*)(x + (size_t)row * d + k);
                } else {
                    int a = k - d;
                    float s; int idx;
                    if (a < 4 * d)      { s = 1.f;        idx = a; }
                    else if (a < 8 * d) { s = g_amp[row]; idx = a - 4 * d; }
                    else                { s = g_att[row]; idx = a - 8 * d; }
                    float4 t4 = *(const float4*)(g_aggs + (size_t)row * 4 * d + idx);
                    v = make_float4(t4.x * s, t4.y * s, t4.z * s, t4.w * s);
                }
            }
            As[kq][m] = v.x; As[kq + 1][m] = v.y; As[kq + 2][m] = v.z; As[kq + 3][m] = v.w;
        }
        // --- B tile (coalesced float4) ---
        #pragma unroll
        for (int e = tid; e < BK * BN / 4; e += NT) {
            int kk = e / (BN / 4);
            int n = (e % (BN / 4)) * 4;
            *(float4*)&Bs[kk][n] = *(const float4*)(W + (size_t)(k0 + kk) * dout + n0 + n);
        }
        __syncthreads();

        #pragma unroll
        for (int kk = 0; kk < BK; kk++) {
            float4 a0 = *(const float4*)&As[kk][tm * 8];
            float4 a1 = *(const float4*)&As[kk][tm * 8 + 4];
            // B pairs are contiguous in shared: read directly as packed b64
            const unsigned long long* bp =
                (const unsigned long long*)&Bs[kk][tn * 8];
            unsigned long long bq0 = bp[0], bq1 = bp[1], bq2 = bp[2], bq3 = bp[3];
            float aa[8] = {a0.x, a0.y, a0.z, a0.w, a1.x, a1.y, a1.z, a1.w};
            #pragma unroll
            for (int i = 0; i < 8; i++) {
                unsigned long long ad;  // (aa[i], aa[i]) — ALU-pipe pack
                asm("mov.b64 %0, {%1, %1};" : "=l"(ad) : "f"(aa[i]));
                asm("fma.rn.f32x2 %0, %1, %2, %0;" : "+l"(acc2[i][0]) : "l"(ad), "l"(bq0));
                asm("fma.rn.f32x2 %0, %1, %2, %0;" : "+l"(acc2[i][1]) : "l"(ad), "l"(bq1));
                asm("fma.rn.f32x2 %0, %1, %2, %0;" : "+l"(acc2[i][2]) : "l"(ad), "l"(bq2));
                asm("fma.rn.f32x2 %0, %1, %2, %0;" : "+l"(acc2[i][3]) : "l"(ad), "l"(bq3));
            }
        }
        __syncthreads();
    }

    float bv[8];
    #pragma unroll
    for (int j = 0; j < 8; j++) bv[j] = bias[n0 + tn * 8 + j];
    #pragma unroll
    for (int i = 0; i < 8; i++) {
        int r = row0 + tm * 8 + i;
        if (r < NN) {
            float c[8];
            #pragma unroll
            for (int j = 0; j < 4; j++) {
                float lo, hi;
                asm("mov.b64 {%0, %1}, %2;" : "=f"(lo), "=f"(hi) : "l"(acc2[i][j]));
                c[2 * j] = lo; c[2 * j + 1] = hi;
            }
            float4 o0, o1;
            o0.x = fmaxf(c[0] + bv[0], 0.f);
            o0.y = fmaxf(c[1] + bv[1], 0.f);
            o0.z = fmaxf(c[2] + bv[2], 0.f);
            o0.w = fmaxf(c[3] + bv[3], 0.f);
            o1.x = fmaxf(c[4] + bv[4], 0.f);
            o1.y = fmaxf(c[5] + bv[5], 0.f);
            o1.z = fmaxf(c[6] + bv[6], 0.f);
            o1.w = fmaxf(c[7] + bv[7], 0.f);
            float* hp = h + (size_t)r * dout + n0 + tn * 8;
            *(float4*)hp = o0;
            *(float4*)(hp + 4) = o1;
        }
    }
}

// ---------------- BatchNorm ----------------
__global__ void k_zerocols() {
    int i = threadIdx.x;
    g_colsum[i] = 0.f; g_colssq[i] = 0.f;
}

__global__ void k_stats(const float* __restrict__ h, int dout) {
    int col = threadIdx.x;           // blockDim.x == dout
    int r0 = blockIdx.x * 256;
    int r1 = min(r0 + 256, NN);
    float s = 0.f, q = 0.f;
    for (int r = r0; r < r1; r++) {
        float v = h[(size_t)r * dout + col];
        s += v; q += v * v;
    }
    atomicAdd(&g_colsum[col], s);
    atomicAdd(&g_colssq[col], q);
}

__global__ void k_bnfinal(const float* __restrict__ gamma, const float* __restrict__ beta, int dout) {
    int c = threadIdx.x;
    if (c >= dout) return;
    float m = g_colsum[c] / (float)NN;
    float var = fmaxf(g_colssq[c] / (float)NN - m * m, 0.f);
    float sc = gamma[c] * rsqrtf(var + EPSL);
    g_scale[c] = sc;
    g_shift[c] = beta[c] - m * sc;
}

__global__ void k_norm(const float* __restrict__ h, float* __restrict__ xo, int dout_mask, int total) {
    int i = blockIdx.x * blockDim.x + threadIdx.x;
    if (i >= total) return;
    int c = i & dout_mask;
    xo[i] = h[i] * g_scale[c] + g_shift[c];
}

// ---------------- classifier ----------------
__global__ void k_cls(const float* __restrict__ Wc, const float* __restrict__ bc, float* __restrict__ out) {
    __shared__ float sw[64 * 10];
    __shared__ float sb[10];
    for (int i = threadIdx.x; i < 640; i += blockDim.x) sw[i] = Wc[i];
    if (threadIdx.x < 10) sb[threadIdx.x] = bc[threadIdx.x];
    __syncthreads();
    int v = blockIdx.x * blockDim.x + threadIdx.x;
    if (v >= NN) return;
    const float* xr = g_x + (size_t)v * 64;
    float acc[10];
    #pragma unroll
    for (int c = 0; c < 10; c++) acc[c] = sb[c];
    #pragma unroll
    for (int f = 0; f < 64; f++) {
        float xv = xr[f];
        #pragma unroll
        for (int c = 0; c < 10; c++) acc[c] += xv * sw[f * 10 + c];
    }
    #pragma unroll
    for (int c = 0; c < 10; c++) out[(size_t)v * 10 + c] = acc[c];
}

// ---------------- launch ----------------
extern "C" void kernel_launch(void* const* d_in, const int* in_sizes, int n_in,
                              void* d_out, int out_size) {
    const float* x0 = (const float*)d_in[0];
    const int*   ei = (const int*)d_in[1];
    const float* W[4]  = {(const float*)d_in[2],  (const float*)d_in[6],
                          (const float*)d_in[10], (const float*)d_in[14]};
    const float* b[4]  = {(const float*)d_in[3],  (const float*)d_in[7],
                          (const float*)d_in[11], (const float*)d_in[15]};
    const float* ga[4] = {(const float*)d_in[4],  (const float*)d_in[8],
                          (const float*)d_in[12], (const float*)d_in[16]};
    const float* be[4] = {(const float*)d_in[5],  (const float*)d_in[9],
                          (const float*)d_in[13], (const float*)d_in[17]};
    const float* Wc = (const float*)d_in[18];
    const float* bc = (const float*)d_in[19];
    float* out = (float*)d_out;

    float *px, *ph;
    cudaGetSymbolAddress((void**)&px, g_x);
    cudaGetSymbolAddress((void**)&ph, g_h);

    const int TB = 256;
    const int NB_N = (NN + TB - 1) / TB;      // 196
    const int NB_E = (EE + TB - 1) / TB;      // 3125

    // prologue (graph structure is fixed across layers)
    k_init<<<NB_N, TB>>>();
    k_deg<<<NB_E, TB>>>(ei);
    k_logdeg<<<NB_N, TB>>>();
    k_ampatt<<<NB_N, TB>>>();
    k_scan1<<<NBLK, 1024>>>();
    k_scan2<<<1, 32>>>();
    k_scan3<<<NB_N, TB>>>();
    k_csr<<<NB_E, TB>>>(ei);

    const int dims[5]  = {64, 128, 256, 128, 64};  // d_in per layer, last = cls input
    const int AGG_B = (NN * 32 + TB - 1) / TB;     // 6250 (warp per node)
    const int GEMM_MB = (NN + 127) / 128;          // 391

    for (int l = 0; l < 4; l++) {
        int d = dims[l], dout = dims[l + 1];
        const float* xin = (l == 0) ? x0 : px;

        switch (d) {
            case 64:  k_agg<2><<<AGG_B, TB>>>(xin); break;
            case 128: k_agg<4><<<AGG_B, TB>>>(xin); break;
            case 256: k_agg<8><<<AGG_B, TB>>>(xin); break;
        }

        if (dout >= 128) {
            dim3 grid(GEMM_MB, dout / 128);
            k_gemm<128><<<grid, 256>>>(xin, W[l], b[l], ph, d, dout);
        } else {
            dim3 grid(GEMM_MB, 1);
            k_gemm<64><<<grid, 128>>>(xin, W[l], b[l], ph, d, dout);
        }

        k_zerocols<<<1, MAXD>>>();
        k_stats<<<(NN + 255) / 256, dout>>>(ph, dout);
        k_bnfinal<<<1, MAXD>>>(ga[l], be[l], dout);

        int total = NN * dout;
        k_norm<<<(total + TB - 1) / TB, TB>>>(ph, px, dout - 1, total);
    }

    k_cls<<<NB_N, TB>>>(Wc, bc, out);
}

// round 12
// speedup vs baseline: 1.4813x; 1.4720x over previous
#include <cuda_runtime.h>
#include <cuda_bf16.h>
#include <math.h>
#include <float.h>
#include <stdint.h>

#define NN   50000
#define EE   800000
#define EPSL 1e-5f
#define NBLK 49   // ceil(NN/1024)
#define MAXK 3328 // 13*256
#define MAXW 425984

// ---------------- scratch (device globals; no allocation) ----------------
__device__ float g_deg[NN];
__device__ float g_logdeg[NN];
__device__ float g_amp[NN];
__device__ float g_att[NN];
__device__ float g_sumlog;
__device__ int   g_off[NN + 1];
__device__ int   g_incl[NN];
__device__ int   g_cur[NN];
__device__ int   g_srcs[EE];
__device__ int   g_bsum[NBLK];
__device__ float g_x[(size_t)NN * 256];          // normalized layer input (fp32)
__device__ float g_h[(size_t)NN * 256];          // relu(linear) output
__device__ float g_colsum[256];
__device__ float g_colssq[256];
__device__ float g_scale[256];
__device__ float g_shift[256];
__device__ __nv_bfloat16 g_fh[(size_t)NN * MAXK];  // feat hi (bf16)  [N][13d]
__device__ __nv_bfloat16 g_fl[(size_t)NN * MAXK];  // feat lo
__device__ __nv_bfloat16 g_wh[MAXW];               // W^T hi  [dout][K]
__device__ __nv_bfloat16 g_wl[MAXW];               // W^T lo

// ---------------- helpers ----------------
__device__ __forceinline__ uint32_t smem_u32(const void* p) {
    uint32_t a;
    asm("{ .reg .u64 t; cvta.to.shared.u64 t, %1; cvt.u32.u64 %0, t; }" : "=r"(a) : "l"(p));
    return a;
}
__device__ __forceinline__ void cp16(uint32_t dst, const void* src) {
    asm volatile("cp.async.cg.shared.global [%0], [%1], 16;" :: "r"(dst), "l"(src));
}
#define CP_COMMIT() asm volatile("cp.async.commit_group;" ::: "memory")
__device__ __forceinline__ void ldsm4(uint32_t* r, uint32_t addr) {
    asm volatile("ldmatrix.sync.aligned.m8n8.x4.shared.b16 {%0,%1,%2,%3}, [%4];"
                 : "=r"(r[0]), "=r"(r[1]), "=r"(r[2]), "=r"(r[3]) : "r"(addr));
}
__device__ __forceinline__ void mma16816(float* c, const uint32_t* a, uint32_t b0, uint32_t b1) {
    asm volatile("mma.sync.aligned.m16n8k16.row.col.f32.bf16.bf16.f32 "
                 "{%0,%1,%2,%3}, {%4,%5,%6,%7}, {%8,%9}, {%0,%1,%2,%3};"
                 : "+f"(c[0]), "+f"(c[1]), "+f"(c[2]), "+f"(c[3])
                 : "r"(a[0]), "r"(a[1]), "r"(a[2]), "r"(a[3]), "r"(b0), "r"(b1));
}
__device__ __forceinline__ void bsplit(float v, __nv_bfloat16& hi, __nv_bfloat16& lo) {
    hi = __float2bfloat16_rn(v);
    lo = __float2bfloat16_rn(v - __bfloat162float(hi));
}

// ---------------- prologue: degrees, scalers, CSR ----------------
__global__ void k_init() {
    int i = blockIdx.x * blockDim.x + threadIdx.x;
    if (i < NN) { g_deg[i] = 0.f; g_cur[i] = 0; }
    if (i == 0) g_sumlog = 0.f;
}
__global__ void k_deg(const int* __restrict__ ei) {
    int e = blockIdx.x * blockDim.x + threadIdx.x;
    if (e < EE) atomicAdd(&g_deg[ei[EE + e]], 1.f);
}
__global__ void k_logdeg() {
    int i = blockIdx.x * blockDim.x + threadIdx.x;
    float v = 0.f;
    if (i < NN) { v = log1pf(g_deg[i]); g_logdeg[i] = v; }
    #pragma unroll
    for (int o = 16; o > 0; o >>= 1) v += __shfl_down_sync(0xFFFFFFFFu, v, o);
    if ((threadIdx.x & 31) == 0) atomicAdd(&g_sumlog, v);
}
__global__ void k_ampatt() {
    int i = blockIdx.x * blockDim.x + threadIdx.x;
    if (i >= NN) return;
    float delta = g_sumlog / (float)NN;
    float ld = g_logdeg[i];
    g_amp[i] = ld / delta;
    g_att[i] = (ld > 0.f) ? (delta / fmaxf(ld, 1e-6f)) : 1.f;
}
__global__ void k_scan1() {
    __shared__ int s[1024];
    int tid = threadIdx.x;
    int i = blockIdx.x * 1024 + tid;
    int v = (i < NN) ? (int)(g_deg[i] + 0.5f) : 0;
    s[tid] = v;
    __syncthreads();
    for (int d = 1; d < 1024; d <<= 1) {
        int t = (tid >= d) ? s[tid - d] : 0;
        __syncthreads();
        s[tid] += t;
        __syncthreads();
    }
    if (i < NN) g_incl[i] = s[tid];
    if (tid == 1023) g_bsum[blockIdx.x] = s[1023];
}
__global__ void k_scan2() {
    if (threadIdx.x == 0) {
        int run = 0;
        for (int b = 0; b < NBLK; b++) { int t = g_bsum[b]; g_bsum[b] = run; run += t; }
    }
}
__global__ void k_scan3() {
    int i = blockIdx.x * blockDim.x + threadIdx.x;
    if (i < NN) {
        int d = (int)(g_deg[i] + 0.5f);
        g_off[i] = g_bsum[i >> 10] + g_incl[i] - d;
    }
    if (i == 0) g_off[NN] = EE;
}
__global__ void k_csr(const int* __restrict__ ei) {
    int e = blockIdx.x * blockDim.x + threadIdx.x;
    if (e >= EE) return;
    int d = ei[EE + e];
    int p = atomicAdd(&g_cur[d], 1);
    g_srcs[g_off[d] + p] = ei[e];
}

// ---------------- W^T hi/lo split ----------------
__global__ void k_wsplit(const float* __restrict__ W, int K, int dout) {
    int i = blockIdx.x * blockDim.x + threadIdx.x;
    if (i >= K * dout) return;
    int k = i / dout, n = i - k * dout;          // coalesced read of W[k][n]
    __nv_bfloat16 hi, lo;
    bsplit(W[i], hi, lo);
    g_wh[(size_t)n * K + k] = hi;
    g_wl[(size_t)n * K + k] = lo;
}

// ---------------- feat x-section for layer 1 ----------------
__global__ void k_featx0(const float* __restrict__ x0) {
    int i = blockIdx.x * blockDim.x + threadIdx.x;   // over N*64
    if (i >= NN * 64) return;
    int row = i >> 6, c = i & 63;
    __nv_bfloat16 hi, lo;
    bsplit(x0[i], hi, lo);
    size_t idx = (size_t)row * 832 + c;
    g_fh[idx] = hi; g_fl[idx] = lo;
}

// ---------------- PNA aggregation: warp per node, writes feat hi/lo ----------------
template <int DJ>
__global__ void k_agg(const float* __restrict__ x) {
    const int d = DJ * 32;
    const int K = 13 * d;
    int gw = (blockIdx.x * blockDim.x + threadIdx.x) >> 5;
    int lane = threadIdx.x & 31;
    if (gw >= NN) return;
    int beg = g_off[gw], end = g_off[gw + 1];
    float sum[DJ], ssq[DJ], mn[DJ], mx[DJ];
    #pragma unroll
    for (int j = 0; j < DJ; j++) { sum[j] = 0.f; ssq[j] = 0.f; mn[j] = FLT_MAX; mx[j] = -FLT_MAX; }
    for (int e = beg; e < end; e++) {
        const float* row = x + (size_t)g_srcs[e] * d;
        #pragma unroll
        for (int j = 0; j < DJ; j++) {
            float v = __ldg(row + lane + 32 * j);
            sum[j] += v; ssq[j] += v * v;
            mn[j] = fminf(mn[j], v); mx[j] = fmaxf(mx[j], v);
        }
    }
    float kf  = (float)(end - beg);
    float inv = 1.f / fmaxf(kf, 1.f);
    float s3[3] = {1.f, g_amp[gw], g_att[gw]};
    size_t base = (size_t)gw * K + d;
    #pragma unroll
    for (int j = 0; j < DJ; j++) {
        int f = lane + 32 * j;
        float mean = sum[j] * inv;
        float msq  = ssq[j] * inv;
        float vals[4];
        vals[0] = mean;
        vals[1] = (kf > 0.f) ? mn[j] : 0.f;
        vals[2] = (kf > 0.f) ? mx[j] : 0.f;
        vals[3] = sqrtf(fmaxf(msq - mean * mean, 0.f) + EPSL);
        #pragma unroll
        for (int sec = 0; sec < 3; sec++)
            #pragma unroll
            for (int a = 0; a < 4; a++) {
                float v = vals[a] * s3[sec];
                __nv_bfloat16 hi, lo;
                bsplit(v, hi, lo);
                size_t idx = base + (size_t)(sec * 4 + a) * d + f;
                g_fh[idx] = hi; g_fl[idx] = lo;
            }
    }
}

// ---------------- mma.sync bf16 GEMM over virtual K' = 3K ----------------
// C = Ah.Bh + Ah.Bl + Al.Bh; chunk c of K'=3K selects (A,B) source pointers.
// BM=128, BK=32, warp tile 64x32, pad-8 rows (conflict-free ldmatrix).
template <int BN, int NW>
__global__ void __launch_bounds__(32 * NW, 2)
k_mma(const __nv_bfloat16* __restrict__ fh, const __nv_bfloat16* __restrict__ fl,
      const __nv_bfloat16* __restrict__ wh, const __nv_bfloat16* __restrict__ wl,
      const float* __restrict__ bias, float* __restrict__ h,
      int K, int dout, int nch) {
    const int NT = 32 * NW;
    const int LD = 40;                       // 32 + 8 pad (halves)
    const int A_ST = 128 * LD;               // halves per A stage
    const int B_ST = BN * LD;
    __shared__ __align__(16) __nv_bfloat16 As[2][A_ST];
    __shared__ __align__(16) __nv_bfloat16 Bs[2][B_ST];

    int tid = threadIdx.x, lane = tid & 31, wid = tid >> 5;
    int warp_m = wid & 1, warp_n = wid >> 1;     // warp tile 64x32
    int row0 = blockIdx.x * 128;
    int n0 = blockIdx.y * BN;
    uint32_t asb = smem_u32(As), bsb = smem_u32(Bs);

    float acc[4][4][4];
    #pragma unroll
    for (int mt = 0; mt < 4; mt++)
        #pragma unroll
        for (int nt = 0; nt < 4; nt++)
            #pragma unroll
            for (int q = 0; q < 4; q++) acc[mt][nt][q] = 0.f;

    // chunk issue: cp.async global -> smem stage `buf`
    auto issue = [&](int c, int buf) {
        int kb = c << 5;
        int sec = kb / K;
        int kk0 = kb - sec * K;
        const __nv_bfloat16* ap = (sec == 2) ? fl : fh;
        const __nv_bfloat16* bp = (sec == 1) ? wl : wh;
        #pragma unroll 2
        for (int i = tid; i < 512; i += NT) {          // A: 128 rows x 4 x 16B
            int r = i >> 2, kq = (i & 3) << 3;
            int rr = row0 + r; if (rr >= NN) rr = NN - 1;
            cp16(asb + (buf * A_ST + r * LD + kq) * 2, ap + (size_t)rr * K + kk0 + kq);
        }
        #pragma unroll 2
        for (int i = tid; i < BN * 4; i += NT) {       // B: BN rows x 4 x 16B
            int n = i >> 2, kq = (i & 3) << 3;
            cp16(bsb + (buf * B_ST + n * LD + kq) * 2, bp + (size_t)(n0 + n) * K + kk0 + kq);
        }
    };

    issue(0, 0);
    CP_COMMIT();

    for (int c = 0; c < nch; c++) {
        int buf = c & 1;
        if (c + 1 < nch) {
            issue(c + 1, buf ^ 1);
            CP_COMMIT();
            asm volatile("cp.async.wait_group 1;" ::: "memory");
        } else {
            asm volatile("cp.async.wait_group 0;" ::: "memory");
        }
        __syncthreads();

        uint32_t a_base = asb + (buf * A_ST) * 2;
        uint32_t b_base = bsb + (buf * B_ST) * 2;
        #pragma unroll
        for (int kk = 0; kk < 32; kk += 16) {
            uint32_t bfr[2][4];
            #pragma unroll
            for (int ntp = 0; ntp < 2; ntp++) {
                uint32_t addr = b_base +
                    ((warp_n * 32 + ntp * 16 + ((lane >> 4) << 3) + (lane & 7)) * LD
                     + kk + (((lane >> 3) & 1) << 3)) * 2;
                ldsm4(bfr[ntp], addr);
            }
            #pragma unroll
            for (int mt = 0; mt < 4; mt++) {
                uint32_t a[4];
                uint32_t addr = a_base +
                    ((warp_m * 64 + mt * 16 + (lane & 15)) * LD
                     + kk + ((lane >> 4) << 3)) * 2;
                ldsm4(a, addr);
                #pragma unroll
                for (int nt = 0; nt < 4; nt++)
                    mma16816(acc[mt][nt], a, bfr[nt >> 1][(nt & 1) * 2],
                             bfr[nt >> 1][(nt & 1) * 2 + 1]);
            }
        }
        __syncthreads();
    }

    // epilogue: bias + relu, write h
    #pragma unroll
    for (int mt = 0; mt < 4; mt++) {
        int r1 = row0 + warp_m * 64 + mt * 16 + (lane >> 2);
        int r2 = r1 + 8;
        #pragma unroll
        for (int nt = 0; nt < 4; nt++) {
            int col = n0 + warp_n * 32 + nt * 8 + 2 * (lane & 3);
            float b0 = bias[col], b1 = bias[col + 1];
            if (r1 < NN) {
                float2 v;
                v.x = fmaxf(acc[mt][nt][0] + b0, 0.f);
                v.y = fmaxf(acc[mt][nt][1] + b1, 0.f);
                *(float2*)(h + (size_t)r1 * dout + col) = v;
            }
            if (r2 < NN) {
                float2 v;
                v.x = fmaxf(acc[mt][nt][2] + b0, 0.f);
                v.y = fmaxf(acc[mt][nt][3] + b1, 0.f);
                *(float2*)(h + (size_t)r2 * dout + col) = v;
            }
        }
    }
}

// ---------------- BatchNorm ----------------
__global__ void k_zerocols() {
    int i = threadIdx.x;
    g_colsum[i] = 0.f; g_colssq[i] = 0.f;
}
__global__ void k_stats(const float* __restrict__ h, int dout) {
    int col = threadIdx.x;
    int r0 = blockIdx.x * 256;
    int r1 = min(r0 + 256, NN);
    float s = 0.f, q = 0.f;
    for (int r = r0; r < r1; r++) {
        float v = h[(size_t)r * dout + col];
        s += v; q += v * v;
    }
    atomicAdd(&g_colsum[col], s);
    atomicAdd(&g_colssq[col], q);
}
__global__ void k_bnfinal(const float* __restrict__ gamma, const float* __restrict__ beta, int dout) {
    int c = threadIdx.x;
    if (c >= dout) return;
    float m = g_colsum[c] / (float)NN;
    float var = fmaxf(g_colssq[c] / (float)NN - m * m, 0.f);
    float sc = gamma[c] * rsqrtf(var + EPSL);
    g_scale[c] = sc;
    g_shift[c] = beta[c] - m * sc;
}
// normalize; also write next layer's feat x-section (bf16 hi/lo) if Knext > 0
__global__ void k_norm(const float* __restrict__ h, float* __restrict__ xo,
                       int lg, int total, int Knext) {
    int i = blockIdx.x * blockDim.x + threadIdx.x;
    if (i >= total) return;
    int c = i & ((1 << lg) - 1);
    float v = h[i] * g_scale[c] + g_shift[c];
    xo[i] = v;
    if (Knext > 0) {
        int row = i >> lg;
        __nv_bfloat16 hi, lo;
        bsplit(v, hi, lo);
        size_t idx = (size_t)row * Knext + c;
        g_fh[idx] = hi; g_fl[idx] = lo;
    }
}

// ---------------- classifier ----------------
__global__ void k_cls(const float* __restrict__ Wc, const float* __restrict__ bc, float* __restrict__ out) {
    __shared__ float sw[64 * 10];
    __shared__ float sb[10];
    for (int i = threadIdx.x; i < 640; i += blockDim.x) sw[i] = Wc[i];
    if (threadIdx.x < 10) sb[threadIdx.x] = bc[threadIdx.x];
    __syncthreads();
    int v = blockIdx.x * blockDim.x + threadIdx.x;
    if (v >= NN) return;
    const float* xr = g_x + (size_t)v * 64;
    float acc[10];
    #pragma unroll
    for (int c = 0; c < 10; c++) acc[c] = sb[c];
    #pragma unroll
    for (int f = 0; f < 64; f++) {
        float xv = xr[f];
        #pragma unroll
        for (int c = 0; c < 10; c++) acc[c] += xv * sw[f * 10 + c];
    }
    #pragma unroll
    for (int c = 0; c < 10; c++) out[(size_t)v * 10 + c] = acc[c];
}

// ---------------- launch ----------------
extern "C" void kernel_launch(void* const* d_in, const int* in_sizes, int n_in,
                              void* d_out, int out_size) {
    const float* x0 = (const float*)d_in[0];
    const int*   ei = (const int*)d_in[1];
    const float* W[4]  = {(const float*)d_in[2],  (const float*)d_in[6],
                          (const float*)d_in[10], (const float*)d_in[14]};
    const float* b[4]  = {(const float*)d_in[3],  (const float*)d_in[7],
                          (const float*)d_in[11], (const float*)d_in[15]};
    const float* ga[4] = {(const float*)d_in[4],  (const float*)d_in[8],
                          (const float*)d_in[12], (const float*)d_in[16]};
    const float* be[4] = {(const float*)d_in[5],  (const float*)d_in[9],
                          (const float*)d_in[13], (const float*)d_in[17]};
    const float* Wc = (const float*)d_in[18];
    const float* bc = (const float*)d_in[19];
    float* out = (float*)d_out;

    float *px, *ph;
    __nv_bfloat16 *pfh, *pfl, *pwh, *pwl;
    cudaGetSymbolAddress((void**)&px, g_x);
    cudaGetSymbolAddress((void**)&ph, g_h);
    cudaGetSymbolAddress((void**)&pfh, g_fh);
    cudaGetSymbolAddress((void**)&pfl, g_fl);
    cudaGetSymbolAddress((void**)&pwh, g_wh);
    cudaGetSymbolAddress((void**)&pwl, g_wl);

    const int TB = 256;
    const int NB_N = (NN + TB - 1) / TB;
    const int NB_E = (EE + TB - 1) / TB;

    k_init<<<NB_N, TB>>>();
    k_deg<<<NB_E, TB>>>(ei);
    k_logdeg<<<NB_N, TB>>>();
    k_ampatt<<<NB_N, TB>>>();
    k_scan1<<<NBLK, 1024>>>();
    k_scan2<<<1, 32>>>();
    k_scan3<<<NB_N, TB>>>();
    k_csr<<<NB_E, TB>>>(ei);
    k_featx0<<<(NN * 64 + TB - 1) / TB, TB>>>(x0);

    const int dims[5] = {64, 128, 256, 128, 64};
    const int lgs[4]  = {7, 8, 7, 6};             // log2(dout)
    const int AGG_B = (NN * 32 + TB - 1) / TB;
    const int MB = (NN + 127) / 128;              // 391

    for (int l = 0; l < 4; l++) {
        int d = dims[l], dout = dims[l + 1];
        int K = 13 * d;
        int nch = 3 * K / 32;
        const float* xin = (l == 0) ? x0 : px;

        k_wsplit<<<(K * dout + TB - 1) / TB, TB>>>(W[l], K, dout);

        switch (d) {
            case 64:  k_agg<2><<<AGG_B, TB>>>(xin); break;
            case 128: k_agg<4><<<AGG_B, TB>>>(xin); break;
            case 256: k_agg<8><<<AGG_B, TB>>>(xin); break;
        }

        if (dout >= 128) {
            dim3 grid(MB, dout / 128);
            k_mma<128, 8><<<grid, 256>>>(pfh, pfl, pwh, pwl, b[l], ph, K, dout, nch);
        } else {
            dim3 grid(MB, 1);
            k_mma<64, 4><<<grid, 128>>>(pfh, pfl, pwh, pwl, b[l], ph, K, dout, nch);
        }

        k_zerocols<<<1, 256>>>();
        k_stats<<<(NN + 255) / 256, dout>>>(ph, dout);
        k_bnfinal<<<1, 256>>>(ga[l], be[l], dout);

        int total = NN * dout;
        int Knext = (l < 3) ? 13 * dims[l + 1] : 0;
        k_norm<<<(total + TB - 1) / TB, TB>>>(ph, px, lgs[l], total, Knext);
    }

    k_cls<<<NB_N, TB>>>(Wc, bc, out);
}

// round 13
// speedup vs baseline: 2.3687x; 1.5991x over previous
#include <cuda_runtime.h>
#include <cuda_bf16.h>
#include <math.h>
#include <float.h>
#include <stdint.h>

#define NN   50000
#define EE   800000
#define EPSL 1e-5f
#define NBLK 49   // ceil(NN/1024)
#define MAXW 425984

// ---------------- scratch (device globals; no allocation) ----------------
__device__ float g_deg[NN];
__device__ float g_logdeg[NN];
__device__ float g_amp[NN];
__device__ float g_att[NN];
__device__ float g_sumlog;
__device__ int   g_off[NN + 1];
__device__ int   g_incl[NN];
__device__ int   g_cur[NN];
__device__ int   g_srcs[EE];
__device__ int   g_bsum[NBLK];
__device__ float g_aggs[(size_t)NN * 1024];      // [N][4d] fp32, d<=256
__device__ float g_x[(size_t)NN * 256];          // normalized layer input (fp32)
__device__ float g_h[(size_t)NN * 256];          // relu(linear) output
__device__ float g_colsum[256];
__device__ float g_colssq[256];
__device__ float g_scale[256];
__device__ float g_shift[256];
__device__ __nv_bfloat16 g_wh[MAXW];             // W^T hi  [dout][K]
__device__ __nv_bfloat16 g_wl[MAXW];             // W^T lo

// ---------------- helpers ----------------
__device__ __forceinline__ uint32_t smem_u32(const void* p) {
    uint32_t a;
    asm("{ .reg .u64 t; cvta.to.shared.u64 t, %1; cvt.u32.u64 %0, t; }" : "=r"(a) : "l"(p));
    return a;
}
__device__ __forceinline__ void cp16(uint32_t dst, const void* src) {
    asm volatile("cp.async.cg.shared.global [%0], [%1], 16;" :: "r"(dst), "l"(src));
}
#define CP_COMMIT() asm volatile("cp.async.commit_group;" ::: "memory")
__device__ __forceinline__ void ldsm4(uint32_t* r, uint32_t addr) {
    asm volatile("ldmatrix.sync.aligned.m8n8.x4.shared.b16 {%0,%1,%2,%3}, [%4];"
                 : "=r"(r[0]), "=r"(r[1]), "=r"(r[2]), "=r"(r[3]) : "r"(addr));
}
__device__ __forceinline__ void mma16816(float* c, const uint32_t* a, uint32_t b0, uint32_t b1) {
    asm volatile("mma.sync.aligned.m16n8k16.row.col.f32.bf16.bf16.f32 "
                 "{%0,%1,%2,%3}, {%4,%5,%6,%7}, {%8,%9}, {%0,%1,%2,%3};"
                 : "+f"(c[0]), "+f"(c[1]), "+f"(c[2]), "+f"(c[3])
                 : "r"(a[0]), "r"(a[1]), "r"(a[2]), "r"(a[3]), "r"(b0), "r"(b1));
}
__device__ __forceinline__ void bsplit(float v, __nv_bfloat16& hi, __nv_bfloat16& lo) {
    hi = __float2bfloat16_rn(v);
    lo = __float2bfloat16_rn(v - __bfloat162float(hi));
}

// ---------------- prologue: degrees, scalers, CSR ----------------
__global__ void k_init() {
    int i = blockIdx.x * blockDim.x + threadIdx.x;
    if (i < NN) { g_deg[i] = 0.f; g_cur[i] = 0; }
    if (i == 0) g_sumlog = 0.f;
}
__global__ void k_deg(const int* __restrict__ ei) {
    int e = blockIdx.x * blockDim.x + threadIdx.x;
    if (e < EE) atomicAdd(&g_deg[ei[EE + e]], 1.f);
}
__global__ void k_logdeg() {
    int i = blockIdx.x * blockDim.x + threadIdx.x;
    float v = 0.f;
    if (i < NN) { v = log1pf(g_deg[i]); g_logdeg[i] = v; }
    #pragma unroll
    for (int o = 16; o > 0; o >>= 1) v += __shfl_down_sync(0xFFFFFFFFu, v, o);
    if ((threadIdx.x & 31) == 0) atomicAdd(&g_sumlog, v);
}
__global__ void k_ampatt() {
    int i = blockIdx.x * blockDim.x + threadIdx.x;
    if (i >= NN) return;
    float delta = g_sumlog / (float)NN;
    float ld = g_logdeg[i];
    g_amp[i] = ld / delta;
    g_att[i] = (ld > 0.f) ? (delta / fmaxf(ld, 1e-6f)) : 1.f;
}
__global__ void k_scan1() {
    __shared__ int s[1024];
    int tid = threadIdx.x;
    int i = blockIdx.x * 1024 + tid;
    int v = (i < NN) ? (int)(g_deg[i] + 0.5f) : 0;
    s[tid] = v;
    __syncthreads();
    for (int d = 1; d < 1024; d <<= 1) {
        int t = (tid >= d) ? s[tid - d] : 0;
        __syncthreads();
        s[tid] += t;
        __syncthreads();
    }
    if (i < NN) g_incl[i] = s[tid];
    if (tid == 1023) g_bsum[blockIdx.x] = s[1023];
}
__global__ void k_scan2() {
    if (threadIdx.x == 0) {
        int run = 0;
        for (int b = 0; b < NBLK; b++) { int t = g_bsum[b]; g_bsum[b] = run; run += t; }
    }
}
__global__ void k_scan3() {
    int i = blockIdx.x * blockDim.x + threadIdx.x;
    if (i < NN) {
        int d = (int)(g_deg[i] + 0.5f);
        g_off[i] = g_bsum[i >> 10] + g_incl[i] - d;
    }
    if (i == 0) g_off[NN] = EE;
}
__global__ void k_csr(const int* __restrict__ ei) {
    int e = blockIdx.x * blockDim.x + threadIdx.x;
    if (e >= EE) return;
    int d = ei[EE + e];
    int p = atomicAdd(&g_cur[d], 1);
    g_srcs[g_off[d] + p] = ei[e];
}

// ---------------- W^T hi/lo split ----------------
__global__ void k_wsplit(const float* __restrict__ W, int K, int dout) {
    int i = blockIdx.x * blockDim.x + threadIdx.x;
    if (i >= K * dout) return;
    int k = i / dout, n = i - k * dout;          // coalesced read of W[k][n]
    __nv_bfloat16 hi, lo;
    bsplit(W[i], hi, lo);
    g_wh[(size_t)n * K + k] = hi;
    g_wl[(size_t)n * K + k] = lo;
}

// ---------------- PNA aggregation: warp per node, writes aggs fp32 [N][4d] ----------------
template <int DJ>
__global__ void k_agg(const float* __restrict__ x) {
    const int d = DJ * 32;
    int gw = (blockIdx.x * blockDim.x + threadIdx.x) >> 5;
    int lane = threadIdx.x & 31;
    if (gw >= NN) return;
    int beg = g_off[gw], end = g_off[gw + 1];
    float sum[DJ], ssq[DJ], mn[DJ], mx[DJ];
    #pragma unroll
    for (int j = 0; j < DJ; j++) { sum[j] = 0.f; ssq[j] = 0.f; mn[j] = FLT_MAX; mx[j] = -FLT_MAX; }
    for (int e = beg; e < end; e++) {
        const float* row = x + (size_t)g_srcs[e] * d;
        #pragma unroll
        for (int j = 0; j < DJ; j++) {
            float v = __ldg(row + lane + 32 * j);
            sum[j] += v; ssq[j] += v * v;
            mn[j] = fminf(mn[j], v); mx[j] = fmaxf(mx[j], v);
        }
    }
    float kf  = (float)(end - beg);
    float inv = 1.f / fmaxf(kf, 1.f);
    float* ag = g_aggs + (size_t)gw * 4 * d;
    #pragma unroll
    for (int j = 0; j < DJ; j++) {
        int f = lane + 32 * j;
        float mean = sum[j] * inv;
        float msq  = ssq[j] * inv;
        float sd   = sqrtf(fmaxf(msq - mean * mean, 0.f) + EPSL);
        ag[f]         = mean;
        ag[d + f]     = (kf > 0.f) ? mn[j] : 0.f;
        ag[2 * d + f] = (kf > 0.f) ? mx[j] : 0.f;
        ag[3 * d + f] = sd;
    }
}

// ---------------- mma.sync GEMM with on-the-fly A scale+split ----------------
// C = feat @ W, feat = [x | aggs | amp*aggs | att*aggs], W^T stored bf16 hi/lo.
// Virtual chunks: xc = d/32 chunks of x, then (kk, v) pairs over aggs with
// per-row scale {1, amp, att}. Each chunk: load fp32 A, scale, split hi/lo
// into smem, 3 MMA passes: Ah*Bh + Ah*Bl + Al*Bh (error ~2^-18).
template <int BN, int NW>
__global__ void __launch_bounds__(32 * NW)
k_mma(const float* __restrict__ xa, const __nv_bfloat16* __restrict__ wh,
      const __nv_bfloat16* __restrict__ wl, const float* __restrict__ bias,
      float* __restrict__ h, int d, int dout) {
    extern __shared__ __align__(16) __nv_bfloat16 sm[];
    const int NT = 32 * NW;
    const int LD = 40;
    const int A_HALF = 128 * LD;
    const int A_BUF = 2 * A_HALF;          // Ah + Al
    const int B_HALF = BN * LD;
    const int B_BUF = 2 * B_HALF;
    __nv_bfloat16* Abase = sm;             // 2 stages of A_BUF
    __nv_bfloat16* Bbase = sm + 2 * A_BUF; // 2 stages of B_BUF

    const int GR = 1024 / NT;              // float4 groups per thread (A chunk = 4096 f32)
    const int TPR = 32 / (4 * GR);         // threads per A row

    int tid = threadIdx.x, lane = tid & 31, wid = tid >> 5;
    int warp_m = wid & 1, warp_n = wid >> 1;
    int row0 = blockIdx.x * 128;
    int n0 = blockIdx.y * BN;
    int K = 13 * d;
    const int xc = d >> 5;
    const int nvc = (13 * d) >> 5;

    int r_a = tid / TPR;
    int c0a = (tid % TPR) * (4 * GR);
    int rowA = min(row0 + r_a, NN - 1);
    float ampv = g_amp[rowA], attv = g_att[rowA];
    const float* xrow = xa + (size_t)rowA * d + c0a;
    const float* arow = g_aggs + (size_t)rowA * (d << 2) + c0a;

    float acc[4][4][4];
    #pragma unroll
    for (int mt = 0; mt < 4; mt++)
        #pragma unroll
        for (int nt = 0; nt < 4; nt++)
            #pragma unroll
            for (int q = 0; q < 4; q++) acc[mt][nt][q] = 0.f;

    // B chunk issue (hi+lo tiles) via cp.async
    auto issueB = [&](int vc, int buf) {
        int koff;
        if (vc < xc) koff = vc << 5;
        else {
            int q = vc - xc, t3 = q / 3, v = q - t3 * 3;
            koff = d + v * (d << 2) + (t3 << 5);
        }
        uint32_t bh = smem_u32(Bbase + buf * B_BUF);
        uint32_t bl = bh + B_HALF * 2;
        for (int i = tid; i < BN * 4; i += NT) {
            int n = i >> 2, c8 = (i & 3) << 3;
            size_t src = (size_t)(n0 + n) * K + koff + c8;
            uint32_t off = (uint32_t)(n * LD + c8) * 2;
            cp16(bh + off, wh + src);
            cp16(bl + off, wl + src);
        }
    };
    // A chunk fp32 source + scale
    auto a_src = [&](int vc, float& sc) -> const float* {
        if (vc < xc) { sc = 1.f; return xrow + (vc << 5); }
        int q = vc - xc, t3 = q / 3, v = q - t3 * 3;
        sc = (v == 0) ? 1.f : ((v == 1) ? ampv : attv);
        return arow + (t3 << 5);
    };

    float4 fa[GR];
    float sc_cur, sc_nxt;
    {
        const float* p = a_src(0, sc_cur);
        #pragma unroll
        for (int g = 0; g < GR; g++) fa[g] = __ldg((const float4*)(p + 4 * g));
    }
    issueB(0, 0);
    CP_COMMIT();

    for (int c = 0; c < nvc; c++) {
        int buf = c & 1;
        // STS: scale + split current A chunk
        {
            __nv_bfloat16* Ah = Abase + buf * A_BUF;
            __nv_bfloat16* Al = Ah + A_HALF;
            int off = r_a * LD + c0a;
            #pragma unroll
            for (int g = 0; g < GR; g++) {
                float v0 = fa[g].x * sc_cur, v1 = fa[g].y * sc_cur;
                float v2 = fa[g].z * sc_cur, v3 = fa[g].w * sc_cur;
                __nv_bfloat16 h0, h1, h2, h3, l0, l1, l2, l3;
                bsplit(v0, h0, l0); bsplit(v1, h1, l1);
                bsplit(v2, h2, l2); bsplit(v3, h3, l3);
                __nv_bfloat162 ha = {h0, h1}, hb = {h2, h3};
                __nv_bfloat162 la = {l0, l1}, lb = {l2, l3};
                uint2 hp = {*(uint32_t*)&ha, *(uint32_t*)&hb};
                uint2 lp = {*(uint32_t*)&la, *(uint32_t*)&lb};
                *(uint2*)(Ah + off + 4 * g) = hp;
                *(uint2*)(Al + off + 4 * g) = lp;
            }
        }
        if (c + 1 < nvc) {
            issueB(c + 1, buf ^ 1);
            CP_COMMIT();
            const float* p = a_src(c + 1, sc_nxt);
            #pragma unroll
            for (int g = 0; g < GR; g++) fa[g] = __ldg((const float4*)(p + 4 * g));
            asm volatile("cp.async.wait_group 1;" ::: "memory");
        } else {
            asm volatile("cp.async.wait_group 0;" ::: "memory");
        }
        __syncthreads();

        uint32_t ah_b = smem_u32(Abase + buf * A_BUF);
        uint32_t al_b = ah_b + A_HALF * 2;
        uint32_t bh_b = smem_u32(Bbase + buf * B_BUF);
        uint32_t bl_b = bh_b + B_HALF * 2;
        #pragma unroll
        for (int kk = 0; kk < 32; kk += 16) {
            uint32_t bh[2][4], bl[2][4];
            #pragma unroll
            for (int ntp = 0; ntp < 2; ntp++) {
                uint32_t off = ((warp_n * 32 + ntp * 16 + ((lane >> 4) << 3) + (lane & 7)) * LD
                                + kk + (((lane >> 3) & 1) << 3)) * 2;
                ldsm4(bh[ntp], bh_b + off);
                ldsm4(bl[ntp], bl_b + off);
            }
            uint32_t aoffs = ((warp_m * 64 + (lane & 15)) * LD + kk + ((lane >> 4) << 3)) * 2;
            #pragma unroll
            for (int mt = 0; mt < 4; mt++) {
                uint32_t a[4];
                ldsm4(a, ah_b + aoffs + mt * 16 * LD * 2);
                #pragma unroll
                for (int nt = 0; nt < 4; nt++) {
                    mma16816(acc[mt][nt], a, bh[nt >> 1][(nt & 1) * 2], bh[nt >> 1][(nt & 1) * 2 + 1]);
                    mma16816(acc[mt][nt], a, bl[nt >> 1][(nt & 1) * 2], bl[nt >> 1][(nt & 1) * 2 + 1]);
                }
            }
            #pragma unroll
            for (int mt = 0; mt < 4; mt++) {
                uint32_t a[4];
                ldsm4(a, al_b + aoffs + mt * 16 * LD * 2);
                #pragma unroll
                for (int nt = 0; nt < 4; nt++)
                    mma16816(acc[mt][nt], a, bh[nt >> 1][(nt & 1) * 2], bh[nt >> 1][(nt & 1) * 2 + 1]);
            }
        }
        __syncthreads();
        sc_cur = sc_nxt;
    }

    // epilogue: bias + relu
    #pragma unroll
    for (int mt = 0; mt < 4; mt++) {
        int r1 = row0 + warp_m * 64 + mt * 16 + (lane >> 2);
        int r2 = r1 + 8;
        #pragma unroll
        for (int nt = 0; nt < 4; nt++) {
            int col = n0 + warp_n * 32 + nt * 8 + 2 * (lane & 3);
            float b0 = bias[col], b1 = bias[col + 1];
            if (r1 < NN) {
                float2 v;
                v.x = fmaxf(acc[mt][nt][0] + b0, 0.f);
                v.y = fmaxf(acc[mt][nt][1] + b1, 0.f);
                *(float2*)(h + (size_t)r1 * dout + col) = v;
            }
            if (r2 < NN) {
                float2 v;
                v.x = fmaxf(acc[mt][nt][2] + b0, 0.f);
                v.y = fmaxf(acc[mt][nt][3] + b1, 0.f);
                *(float2*)(h + (size_t)r2 * dout + col) = v;
            }
        }
    }
}

// ---------------- BatchNorm ----------------
__global__ void k_zerocols() {
    int i = threadIdx.x;
    g_colsum[i] = 0.f; g_colssq[i] = 0.f;
}
__global__ void k_stats(const float* __restrict__ h, int dout) {
    int col = threadIdx.x;
    int r0 = blockIdx.x * 256;
    int r1 = min(r0 + 256, NN);
    float s = 0.f, q = 0.f;
    for (int r = r0; r < r1; r++) {
        float v = h[(size_t)r * dout + col];
        s += v; q += v * v;
    }
    atomicAdd(&g_colsum[col], s);
    atomicAdd(&g_colssq[col], q);
}
__global__ void k_bnfinal(const float* __restrict__ gamma, const float* __restrict__ beta, int dout) {
    int c = threadIdx.x;
    if (c >= dout) return;
    float m = g_colsum[c] / (float)NN;
    float var = fmaxf(g_colssq[c] / (float)NN - m * m, 0.f);
    float sc = gamma[c] * rsqrtf(var + EPSL);
    g_scale[c] = sc;
    g_shift[c] = beta[c] - m * sc;
}
__global__ void k_norm(const float* __restrict__ h, float* __restrict__ xo, int dout_mask, int total) {
    int i = blockIdx.x * blockDim.x + threadIdx.x;
    if (i >= total) return;
    int c = i & dout_mask;
    xo[i] = h[i] * g_scale[c] + g_shift[c];
}

// ---------------- classifier ----------------
__global__ void k_cls(const float* __restrict__ Wc, const float* __restrict__ bc, float* __restrict__ out) {
    __shared__ float sw[64 * 10];
    __shared__ float sb[10];
    for (int i = threadIdx.x; i < 640; i += blockDim.x) sw[i] = Wc[i];
    if (threadIdx.x < 10) sb[threadIdx.x] = bc[threadIdx.x];
    __syncthreads();
    int v = blockIdx.x * blockDim.x + threadIdx.x;
    if (v >= NN) return;
    const float* xr = g_x + (size_t)v * 64;
    float acc[10];
    #pragma unroll
    for (int c = 0; c < 10; c++) acc[c] = sb[c];
    #pragma unroll
    for (int f = 0; f < 64; f++) {
        float xv = xr[f];
        #pragma unroll
        for (int c = 0; c < 10; c++) acc[c] += xv * sw[f * 10 + c];
    }
    #pragma unroll
    for (int c = 0; c < 10; c++) out[(size_t)v * 10 + c] = acc[c];
}

// ---------------- launch ----------------
extern "C" void kernel_launch(void* const* d_in, const int* in_sizes, int n_in,
                              void* d_out, int out_size) {
    const float* x0 = (const float*)d_in[0];
    const int*   ei = (const int*)d_in[1];
    const float* W[4]  = {(const float*)d_in[2],  (const float*)d_in[6],
                          (const float*)d_in[10], (const float*)d_in[14]};
    const float* b[4]  = {(const float*)d_in[3],  (const float*)d_in[7],
                          (const float*)d_in[11], (const float*)d_in[15]};
    const float* ga[4] = {(const float*)d_in[4],  (const float*)d_in[8],
                          (const float*)d_in[12], (const float*)d_in[16]};
    const float* be[4] = {(const float*)d_in[5],  (const float*)d_in[9],
                          (const float*)d_in[13], (const float*)d_in[17]};
    const float* Wc = (const float*)d_in[18];
    const float* bc = (const float*)d_in[19];
    float* out = (float*)d_out;

    float *px, *ph;
    __nv_bfloat16 *pwh, *pwl;
    cudaGetSymbolAddress((void**)&px, g_x);
    cudaGetSymbolAddress((void**)&ph, g_h);
    cudaGetSymbolAddress((void**)&pwh, g_wh);
    cudaGetSymbolAddress((void**)&pwl, g_wl);

    // dynamic smem: 2*(Ah+Al) + 2*(Bh+Bl) stages, halves * 2B
    const int SM128 = (2 * 2 * 128 * 40 + 2 * 2 * 128 * 40) * 2;  // 81920
    const int SM64  = (2 * 2 * 128 * 40 + 2 * 2 * 64 * 40) * 2;   // 61440
    cudaFuncSetAttribute(k_mma<128, 8>, cudaFuncAttributeMaxDynamicSharedMemorySize, SM128);
    cudaFuncSetAttribute(k_mma<64, 4>,  cudaFuncAttributeMaxDynamicSharedMemorySize, SM64);

    const int TB = 256;
    const int NB_N = (NN + TB - 1) / TB;
    const int NB_E = (EE + TB - 1) / TB;

    k_init<<<NB_N, TB>>>();
    k_deg<<<NB_E, TB>>>(ei);
    k_logdeg<<<NB_N, TB>>>();
    k_ampatt<<<NB_N, TB>>>();
    k_scan1<<<NBLK, 1024>>>();
    k_scan2<<<1, 32>>>();
    k_scan3<<<NB_N, TB>>>();
    k_csr<<<NB_E, TB>>>(ei);

    const int dims[5] = {64, 128, 256, 128, 64};
    const int AGG_B = (NN * 32 + TB - 1) / TB;
    const int MB = (NN + 127) / 128;              // 391

    for (int l = 0; l < 4; l++) {
        int d = dims[l], dout = dims[l + 1];
        int K = 13 * d;
        const float* xin = (l == 0) ? x0 : px;

        k_wsplit<<<(K * dout + TB - 1) / TB, TB>>>(W[l], K, dout);

        switch (d) {
            case 64:  k_agg<2><<<AGG_B, TB>>>(xin); break;
            case 128: k_agg<4><<<AGG_B, TB>>>(xin); break;
            case 256: k_agg<8><<<AGG_B, TB>>>(xin); break;
        }

        if (dout >= 128) {
            dim3 grid(MB, dout / 128);
            k_mma<128, 8><<<grid, 256, SM128>>>(xin, pwh, pwl, b[l], ph, d, dout);
        } else {
            dim3 grid(MB, 1);
            k_mma<64, 4><<<grid, 128, SM64>>>(xin, pwh, pwl, b[l], ph, d, dout);
        }

        k_zerocols<<<1, 256>>>();
        k_stats<<<(NN + 255) / 256, dout>>>(ph, dout);
        k_bnfinal<<<1, 256>>>(ga[l], be[l], dout);

        int total = NN * dout;
        k_norm<<<(total + TB - 1) / TB, TB>>>(ph, px, dout - 1, total);
    }

    k_cls<<<NB_N, TB>>>(Wc, bc, out);
}

// round 15
// speedup vs baseline: 2.5254x; 1.0662x over previous
#include <cuda_runtime.h>
#include <cuda_bf16.h>
#include <math.h>
#include <float.h>
#include <stdint.h>

#define NN   50000
#define EE   800000
#define EPSL 1e-5f
#define NBLK 49   // ceil(NN/1024)
#define MAXW 1064960  // all 4 layers' W^T

// ---------------- scratch (device globals; no allocation) ----------------
__device__ float g_deg[NN];
__device__ float g_logdeg[NN];
__device__ float g_amp[NN];
__device__ float g_att[NN];
__device__ float g_sumlog;
__device__ int   g_off[NN + 1];
__device__ int   g_incl[NN];
__device__ int   g_cur[NN];
__device__ int   g_srcs[EE];
__device__ int   g_bsum[NBLK];
__device__ float g_aggs[(size_t)NN * 1024];      // [N][4d] fp32, d<=256
__device__ float g_x[(size_t)NN * 256];          // normalized layer input (fp32)
__device__ float g_h[(size_t)NN * 256];          // relu(linear) output
__device__ float g_colsum[256];
__device__ float g_colssq[256];
__device__ float g_scale[256];
__device__ float g_shift[256];
__device__ __nv_bfloat16 g_wh[MAXW];             // W^T hi  [dout][K], per-layer offsets
__device__ __nv_bfloat16 g_wl[MAXW];             // W^T lo

// ---------------- helpers ----------------
__device__ __forceinline__ uint32_t smem_u32(const void* p) {
    uint32_t a;
    asm("{ .reg .u64 t; cvta.to.shared.u64 t, %1; cvt.u32.u64 %0, t; }" : "=r"(a) : "l"(p));
    return a;
}
__device__ __forceinline__ void cp16(uint32_t dst, const void* src) {
    asm volatile("cp.async.cg.shared.global [%0], [%1], 16;" :: "r"(dst), "l"(src));
}
#define CP_COMMIT() asm volatile("cp.async.commit_group;" ::: "memory")
__device__ __forceinline__ void ldsm4(uint32_t* r, uint32_t addr) {
    asm volatile("ldmatrix.sync.aligned.m8n8.x4.shared.b16 {%0,%1,%2,%3}, [%4];"
                 : "=r"(r[0]), "=r"(r[1]), "=r"(r[2]), "=r"(r[3]) : "r"(addr));
}
__device__ __forceinline__ void mma16816(float* c, const uint32_t* a, uint32_t b0, uint32_t b1) {
    asm volatile("mma.sync.aligned.m16n8k16.row.col.f32.bf16.bf16.f32 "
                 "{%0,%1,%2,%3}, {%4,%5,%6,%7}, {%8,%9}, {%0,%1,%2,%3};"
                 : "+f"(c[0]), "+f"(c[1]), "+f"(c[2]), "+f"(c[3])
                 : "r"(a[0]), "r"(a[1]), "r"(a[2]), "r"(a[3]), "r"(b0), "r"(b1));
}
__device__ __forceinline__ void bsplit(float v, __nv_bfloat16& hi, __nv_bfloat16& lo) {
    hi = __float2bfloat16_rn(v);
    lo = __float2bfloat16_rn(v - __bfloat162float(hi));
}

// ---------------- prologue: degrees, scalers, CSR ----------------
__global__ void k_init() {
    int i = blockIdx.x * blockDim.x + threadIdx.x;
    if (i < NN) { g_deg[i] = 0.f; g_cur[i] = 0; }
    if (i == 0) g_sumlog = 0.f;
}
__global__ void k_deg(const int* __restrict__ ei) {
    int e = blockIdx.x * blockDim.x + threadIdx.x;
    if (e < EE) atomicAdd(&g_deg[ei[EE + e]], 1.f);
}
__global__ void k_logdeg() {
    int i = blockIdx.x * blockDim.x + threadIdx.x;
    float v = 0.f;
    if (i < NN) { v = log1pf(g_deg[i]); g_logdeg[i] = v; }
    #pragma unroll
    for (int o = 16; o > 0; o >>= 1) v += __shfl_down_sync(0xFFFFFFFFu, v, o);
    if ((threadIdx.x & 31) == 0) atomicAdd(&g_sumlog, v);
}
__global__ void k_ampatt() {
    int i = blockIdx.x * blockDim.x + threadIdx.x;
    if (i >= NN) return;
    float delta = g_sumlog / (float)NN;
    float ld = g_logdeg[i];
    g_amp[i] = ld / delta;
    g_att[i] = (ld > 0.f) ? (delta / fmaxf(ld, 1e-6f)) : 1.f;
}
__global__ void k_scan1() {
    __shared__ int s[1024];
    int tid = threadIdx.x;
    int i = blockIdx.x * 1024 + tid;
    int v = (i < NN) ? (int)(g_deg[i] + 0.5f) : 0;
    s[tid] = v;
    __syncthreads();
    for (int d = 1; d < 1024; d <<= 1) {
        int t = (tid >= d) ? s[tid - d] : 0;
        __syncthreads();
        s[tid] += t;
        __syncthreads();
    }
    if (i < NN) g_incl[i] = s[tid];
    if (tid == 1023) g_bsum[blockIdx.x] = s[1023];
}
__global__ void k_scan2() {
    if (threadIdx.x == 0) {
        int run = 0;
        for (int b = 0; b < NBLK; b++) { int t = g_bsum[b]; g_bsum[b] = run; run += t; }
    }
}
__global__ void k_scan3() {
    int i = blockIdx.x * blockDim.x + threadIdx.x;
    if (i < NN) {
        int d = (int)(g_deg[i] + 0.5f);
        g_off[i] = g_bsum[i >> 10] + g_incl[i] - d;
    }
    if (i == 0) g_off[NN] = EE;
}
__global__ void k_csr(const int* __restrict__ ei) {
    int e = blockIdx.x * blockDim.x + threadIdx.x;
    if (e >= EE) return;
    int d = ei[EE + e];
    int p = atomicAdd(&g_cur[d], 1);
    g_srcs[g_off[d] + p] = ei[e];
}

// ---------------- W^T hi/lo split (into per-layer offset) ----------------
__global__ void k_wsplit(const float* __restrict__ W, int K, int dout, int ofs) {
    int i = blockIdx.x * blockDim.x + threadIdx.x;
    if (i >= K * dout) return;
    int k = i / dout, n = i - k * dout;          // coalesced read of W[k][n]
    __nv_bfloat16 hi, lo;
    bsplit(W[i], hi, lo);
    g_wh[ofs + (size_t)n * K + k] = hi;
    g_wl[ofs + (size_t)n * K + k] = lo;
}

// ---------------- PNA aggregation: warp per node, writes aggs fp32 [N][4d] ----------------
template <int DJ>
__global__ void k_agg(const float* __restrict__ x) {
    const int d = DJ * 32;
    int gw = (blockIdx.x * blockDim.x + threadIdx.x) >> 5;
    int lane = threadIdx.x & 31;
    if (gw >= NN) return;
    int beg = g_off[gw], end = g_off[gw + 1];
    float sum[DJ], ssq[DJ], mn[DJ], mx[DJ];
    #pragma unroll
    for (int j = 0; j < DJ; j++) { sum[j] = 0.f; ssq[j] = 0.f; mn[j] = FLT_MAX; mx[j] = -FLT_MAX; }
    for (int e = beg; e < end; e++) {
        const float* row = x + (size_t)g_srcs[e] * d;
        #pragma unroll
        for (int j = 0; j < DJ; j++) {
            float v = __ldg(row + lane + 32 * j);
            sum[j] += v; ssq[j] += v * v;
            mn[j] = fminf(mn[j], v); mx[j] = fmaxf(mx[j], v);
        }
    }
    float kf  = (float)(end - beg);
    float inv = 1.f / fmaxf(kf, 1.f);
    float* ag = g_aggs + (size_t)gw * 4 * d;
    #pragma unroll
    for (int j = 0; j < DJ; j++) {
        int f = lane + 32 * j;
        float mean = sum[j] * inv;
        float msq  = ssq[j] * inv;
        float sd   = sqrtf(fmaxf(msq - mean * mean, 0.f) + EPSL);
        ag[f]         = mean;
        ag[d + f]     = (kf > 0.f) ? mn[j] : 0.f;
        ag[2 * d + f] = (kf > 0.f) ? mx[j] : 0.f;
        ag[3 * d + f] = sd;
    }
}

// ---------------- mma.sync GEMM with on-the-fly A scale+split ----------------
// grid(dout/BN, MB): n-blocks adjacent -> twin blocks of same row-block run in
// the same wave and share A reads through L2. One __syncthreads per chunk.
template <int BN, int NW>
__global__ void __launch_bounds__(32 * NW, 2)
k_mma(const float* __restrict__ xa, const __nv_bfloat16* __restrict__ wh,
      const __nv_bfloat16* __restrict__ wl, const float* __restrict__ bias,
      float* __restrict__ h, int d, int dout) {
    extern __shared__ __align__(16) __nv_bfloat16 sm[];
    const int NT = 32 * NW;
    const int LD = 40;
    const int A_HALF = 128 * LD;
    const int A_BUF = 2 * A_HALF;          // Ah + Al
    const int B_HALF = BN * LD;
    const int B_BUF = 2 * B_HALF;
    __nv_bfloat16* Abase = sm;             // 2 stages of A_BUF
    __nv_bfloat16* Bbase = sm + 2 * A_BUF; // 2 stages of B_BUF

    const int GR = 1024 / NT;              // float4 groups per thread (A chunk = 4096 f32)
    const int TPR = 32 / (4 * GR);         // threads per A row

    int tid = threadIdx.x, lane = tid & 31, wid = tid >> 5;
    int warp_m = wid & 1, warp_n = wid >> 1;
    int row0 = blockIdx.y * 128;
    int n0 = blockIdx.x * BN;
    int K = 13 * d;
    const int xc = d >> 5;
    const int nvc = (13 * d) >> 5;

    int r_a = tid / TPR;
    int c0a = (tid % TPR) * (4 * GR);
    int rowA = min(row0 + r_a, NN - 1);
    float ampv = g_amp[rowA], attv = g_att[rowA];
    const float* xrow = xa + (size_t)rowA * d + c0a;
    const float* arow = g_aggs + (size_t)rowA * (d << 2) + c0a;

    float acc[4][4][4];
    #pragma unroll
    for (int mt = 0; mt < 4; mt++)
        #pragma unroll
        for (int nt = 0; nt < 4; nt++)
            #pragma unroll
            for (int q = 0; q < 4; q++) acc[mt][nt][q] = 0.f;

    // B chunk issue (hi+lo tiles) via cp.async
    auto issueB = [&](int vc, int buf) {
        int koff;
        if (vc < xc) koff = vc << 5;
        else {
            int q = vc - xc, t3 = q / 3, v = q - t3 * 3;
            koff = d + v * (d << 2) + (t3 << 5);
        }
        uint32_t bh = smem_u32(Bbase + buf * B_BUF);
        uint32_t bl = bh + B_HALF * 2;
        for (int i = tid; i < BN * 4; i += NT) {
            int n = i >> 2, c8 = (i & 3) << 3;
            size_t src = (size_t)(n0 + n) * K + koff + c8;
            uint32_t off = (uint32_t)(n * LD + c8) * 2;
            cp16(bh + off, wh + src);
            cp16(bl + off, wl + src);
        }
    };
    // A chunk fp32 source + scale
    auto a_src = [&](int vc, float& sc) -> const float* {
        if (vc < xc) { sc = 1.f; return xrow + (vc << 5); }
        int q = vc - xc, t3 = q / 3, v = q - t3 * 3;
        sc = (v == 0) ? 1.f : ((v == 1) ? ampv : attv);
        return arow + (t3 << 5);
    };

    float4 fa[GR];
    float sc_cur, sc_nxt;
    {
        const float* p = a_src(0, sc_cur);
        #pragma unroll
        for (int g = 0; g < GR; g++) fa[g] = __ldg((const float4*)(p + 4 * g));
    }
    issueB(0, 0);
    CP_COMMIT();

    for (int c = 0; c < nvc; c++) {
        int buf = c & 1;
        // STS: scale + split current A chunk (independent of B arrival)
        {
            __nv_bfloat16* Ah = Abase + buf * A_BUF;
            __nv_bfloat16* Al = Ah + A_HALF;
            int off = r_a * LD + c0a;
            #pragma unroll
            for (int g = 0; g < GR; g++) {
                float v0 = fa[g].x * sc_cur, v1 = fa[g].y * sc_cur;
                float v2 = fa[g].z * sc_cur, v3 = fa[g].w * sc_cur;
                __nv_bfloat16 h0, h1, h2, h3, l0, l1, l2, l3;
                bsplit(v0, h0, l0); bsplit(v1, h1, l1);
                bsplit(v2, h2, l2); bsplit(v3, h3, l3);
                __nv_bfloat162 ha = {h0, h1}, hb = {h2, h3};
                __nv_bfloat162 la = {l0, l1}, lb = {l2, l3};
                uint2 hp = {*(uint32_t*)&ha, *(uint32_t*)&hb};
                uint2 lp = {*(uint32_t*)&la, *(uint32_t*)&lb};
                *(uint2*)(Ah + off + 4 * g) = hp;
                *(uint2*)(Al + off + 4 * g) = lp;
            }
        }
        asm volatile("cp.async.wait_group 0;" ::: "memory");  // B(c) resident
        __syncthreads();
        if (c + 1 < nvc) {
            issueB(c + 1, buf ^ 1);          // safe: post-sync, MMA(c-1) done everywhere
            CP_COMMIT();
            const float* p = a_src(c + 1, sc_nxt);
            #pragma unroll
            for (int g = 0; g < GR; g++) fa[g] = __ldg((const float4*)(p + 4 * g));
        }

        uint32_t ah_b = smem_u32(Abase + buf * A_BUF);
        uint32_t al_b = ah_b + A_HALF * 2;
        uint32_t bh_b = smem_u32(Bbase + buf * B_BUF);
        uint32_t bl_b = bh_b + B_HALF * 2;
        #pragma unroll
        for (int kk = 0; kk < 32; kk += 16) {
            uint32_t bh[2][4], bl[2][4];
            #pragma unroll
            for (int ntp = 0; ntp < 2; ntp++) {
                uint32_t off = ((warp_n * 32 + ntp * 16 + ((lane >> 4) << 3) + (lane & 7)) * LD
                                + kk + (((lane >> 3) & 1) << 3)) * 2;
                ldsm4(bh[ntp], bh_b + off);
                ldsm4(bl[ntp], bl_b + off);
            }
            uint32_t aoffs = ((warp_m * 64 + (lane & 15)) * LD + kk + ((lane >> 4) << 3)) * 2;
            #pragma unroll
            for (int mt = 0; mt < 4; mt++) {
                uint32_t a[4];
                ldsm4(a, ah_b + aoffs + mt * 16 * LD * 2);
                #pragma unroll
                for (int nt = 0; nt < 4; nt++) {
                    mma16816(acc[mt][nt], a, bh[nt >> 1][(nt & 1) * 2], bh[nt >> 1][(nt & 1) * 2 + 1]);
                    mma16816(acc[mt][nt], a, bl[nt >> 1][(nt & 1) * 2], bl[nt >> 1][(nt & 1) * 2 + 1]);
                }
            }
            #pragma unroll
            for (int mt = 0; mt < 4; mt++) {
                uint32_t a[4];
                ldsm4(a, al_b + aoffs + mt * 16 * LD * 2);
                #pragma unroll
                for (int nt = 0; nt < 4; nt++)
                    mma16816(acc[mt][nt], a, bh[nt >> 1][(nt & 1) * 2], bh[nt >> 1][(nt & 1) * 2 + 1]);
            }
        }
        sc_cur = sc_nxt;
    }

    // epilogue: bias + relu
    #pragma unroll
    for (int mt = 0; mt < 4; mt++) {
        int r1 = row0 + warp_m * 64 + mt * 16 + (lane >> 2);
        int r2 = r1 + 8;
        #pragma unroll
        for (int nt = 0; nt < 4; nt++) {
            int col = n0 + warp_n * 32 + nt * 8 + 2 * (lane & 3);
            float b0 = bias[col], b1 = bias[col + 1];
            if (r1 < NN) {
                float2 v;
                v.x = fmaxf(acc[mt][nt][0] + b0, 0.f);
                v.y = fmaxf(acc[mt][nt][1] + b1, 0.f);
                *(float2*)(h + (size_t)r1 * dout + col) = v;
            }
            if (r2 < NN) {
                float2 v;
                v.x = fmaxf(acc[mt][nt][2] + b0, 0.f);
                v.y = fmaxf(acc[mt][nt][3] + b1, 0.f);
                *(float2*)(h + (size_t)r2 * dout + col) = v;
            }
        }
    }
}

// ---------------- BatchNorm ----------------
__global__ void k_zerocols() {
    int i = threadIdx.x;
    g_colsum[i] = 0.f; g_colssq[i] = 0.f;
}
__global__ void k_stats(const float* __restrict__ h, int dout) {
    int col = threadIdx.x;
    int r0 = blockIdx.x * 256;
    int r1 = min(r0 + 256, NN);
    float s = 0.f, q = 0.f;
    for (int r = r0; r < r1; r++) {
        float v = h[(size_t)r * dout + col];
        s += v; q += v * v;
    }
    atomicAdd(&g_colsum[col], s);
    atomicAdd(&g_colssq[col], q);
}
__global__ void k_bnfinal(const float* __restrict__ gamma, const float* __restrict__ beta, int dout) {
    int c = threadIdx.x;
    if (c >= dout) return;
    float m = g_colsum[c] / (float)NN;
    float var = fmaxf(g_colssq[c] / (float)NN - m * m, 0.f);
    float sc = gamma[c] * rsqrtf(var + EPSL);
    g_scale[c] = sc;
    g_shift[c] = beta[c] - m * sc;
}
__global__ void k_norm(const float* __restrict__ h, float* __restrict__ xo, int dout_mask, int total) {
    int i = blockIdx.x * blockDim.x + threadIdx.x;
    if (i >= total) return;
    int c = i & dout_mask;
    xo[i] = h[i] * g_scale[c] + g_shift[c];
}

// ---------------- classifier ----------------
__global__ void k_cls(const float* __restrict__ Wc, const float* __restrict__ bc, float* __restrict__ out) {
    __shared__ float sw[64 * 10];
    __shared__ float sb[10];
    for (int i = threadIdx.x; i < 640; i += blockDim.x) sw[i] = Wc[i];
    if (threadIdx.x < 10) sb[threadIdx.x] = bc[threadIdx.x];
    __syncthreads();
    int v = blockIdx.x * blockDim.x + threadIdx.x;
    if (v >= NN) return;
    const float* xr = g_x + (size_t)v * 64;
    float acc[10];
    #pragma unroll
    for (int c = 0; c < 10; c++) acc[c] = sb[c];
    #pragma unroll
    for (int f = 0; f < 64; f++) {
        float xv = xr[f];
        #pragma unroll
        for (int c = 0; c < 10; c++) acc[c] += xv * sw[f * 10 + c];
    }
    #pragma unroll
    for (int c = 0; c < 10; c++) out[(size_t)v * 10 + c] = acc[c];
}

// ---------------- launch ----------------
extern "C" void kernel_launch(void* const* d_in, const int* in_sizes, int n_in,
                              void* d_out, int out_size) {
    const float* x0 = (const float*)d_in[0];
    const int*   ei = (const int*)d_in[1];
    const float* W[4]  = {(const float*)d_in[2],  (const float*)d_in[6],
                          (const float*)d_in[10], (const float*)d_in[14]};
    const float* b[4]  = {(const float*)d_in[3],  (const float*)d_in[7],
                          (const float*)d_in[11], (const float*)d_in[15]};
    const float* ga[4] = {(const float*)d_in[4],  (const float*)d_in[8],
                          (const float*)d_in[12], (const float*)d_in[16]};
    const float* be[4] = {(const float*)d_in[5],  (const float*)d_in[9],
                          (const float*)d_in[13], (const float*)d_in[17]};
    const float* Wc = (const float*)d_in[18];
    const float* bc = (const float*)d_in[19];
    float* out = (float*)d_out;

    float *px, *ph;
    __nv_bfloat16 *pwh, *pwl;
    cudaGetSymbolAddress((void**)&px, g_x);
    cudaGetSymbolAddress((void**)&ph, g_h);
    cudaGetSymbolAddress((void**)&pwh, g_wh);
    cudaGetSymbolAddress((void**)&pwl, g_wl);

    // dynamic smem: 2*(Ah+Al) + 2*(Bh+Bl) stages, halves * 2B
    const int SM128 = (2 * 2 * 128 * 40 + 2 * 2 * 128 * 40) * 2;  // 81920
    const int SM64  = (2 * 2 * 128 * 40 + 2 * 2 * 64 * 40) * 2;   // 61440
    cudaFuncSetAttribute(k_mma<128, 8>, cudaFuncAttributeMaxDynamicSharedMemorySize, SM128);
    cudaFuncSetAttribute(k_mma<64, 4>,  cudaFuncAttributeMaxDynamicSharedMemorySize, SM64);

    const int TB = 256;
    const int NB_N = (NN + TB - 1) / TB;
    const int NB_E = (EE + TB - 1) / TB;

    k_init<<<NB_N, TB>>>();
    k_deg<<<NB_E, TB>>>(ei);
    k_logdeg<<<NB_N, TB>>>();
    k_ampatt<<<NB_N, TB>>>();
    k_scan1<<<NBLK, 1024>>>();
    k_scan2<<<1, 32>>>();
    k_scan3<<<NB_N, TB>>>();
    k_csr<<<NB_E, TB>>>(ei);

    const int dims[5] = {64, 128, 256, 128, 64};
    const int wofs[4] = {0, 106496, 532480, 958464};
    // hoist all weight splits (independent of layer chain)
    for (int l = 0; l < 4; l++) {
        int K = 13 * dims[l], dout = dims[l + 1];
        k_wsplit<<<(K * dout + TB - 1) / TB, TB>>>(W[l], K, dout, wofs[l]);
    }

    const int AGG_B = (NN * 32 + TB - 1) / TB;
    const int MB = (NN + 127) / 128;              // 391

    for (int l = 0; l < 4; l++) {
        int d = dims[l], dout = dims[l + 1];
        const float* xin = (l == 0) ? x0 : px;

        switch (d) {
            case 64:  k_agg<2><<<AGG_B, TB>>>(xin); break;
            case 128: k_agg<4><<<AGG_B, TB>>>(xin); break;
            case 256: k_agg<8><<<AGG_B, TB>>>(xin); break;
        }

        if (dout >= 128) {
            dim3 grid(dout / 128, MB);
            k_mma<128, 8><<<grid, 256, SM128>>>(xin, pwh + wofs[l], pwl + wofs[l], b[l], ph, d, dout);
        } else {
            dim3 grid(1, MB);
            k_mma<64, 4><<<grid, 128, SM64>>>(xin, pwh + wofs[l], pwl + wofs[l], b[l], ph, d, dout);
        }

        k_zerocols<<<1, 256>>>();
        k_stats<<<(NN + 255) / 256, dout>>>(ph, dout);
        k_bnfinal<<<1, 256>>>(ga[l], be[l], dout);

        int total = NN * dout;
        k_norm<<<(total + TB - 1) / TB, TB>>>(ph, px, dout - 1, total);
    }

    k_cls<<<NB_N, TB>>>(Wc, bc, out);
}